// round 15
// baseline (speedup 1.0000x reference)
#include <cuda_runtime.h>
#include <cstdint>

#define BB 1024
#define TT 2048
#define FF 16
#define SS 300    // FORWARD_STEPS
#define BPB 7     // batch elements per block
#define GRID 147  // ceil(1024/7); occ 1 -> all blocks co-resident
#define NT 320    // >= SS: one thread per step
#define ITERS 14  // ceil(BPB*SS*2 / NT) = ceil(4200/320)

// Cross-block state, zeroed by a memset node before each kernel replay.
// Each mask word gets its OWN 128B cache line: 44K atomicOrs previously hit
// ~10 lines (~10 LTS slices -> ~4.4K serialized atomics each, the hidden
// multi-microsecond cost). Padded, the addr->LTS hash spreads 300 lines
// across ~184 slices -> ~240 atomics/slice, negligible.
struct MaskLine { unsigned v; unsigned pad[31]; };
struct SyncState {
    MaskLine mask[SS];   // 38.4 KB
    unsigned arrive;     // grid-barrier arrival counter
};
__device__ SyncState g_state;

// ---------------------------------------------------------------------------
// Single persistent kernel, 147 blocks x 320 threads, 1 CTA/SM (R14 base;
// only the mask layout changed).
// Block k owns batches [k*7, k*7+nb). Thread t (< 300) owns step t.
//
// Phase 1: chunk-coalesced, front-batched staging (thread i loads the i-th
//   16B chunk; warp touches 8 lines per LDG.128; all ~14 loads in flight).
// Phase 2: y_j once per (b,j) with the reference's exact _rn op order,
//   overlapped with in-flight loads.
// Phase 3: drain to smem; sync; register-resident gather; <=1 padded
//   atomicOr per (block, step); 147-arrival spin barrier; emit.
//
// Bit-exactness: identical _rn op sequences; y_j >= 0 -> SS-1 clamp == TT-1
// clamp (rel_err 0.0 on every passing round since R2).
// ---------------------------------------------------------------------------
__global__ void __launch_bounds__(NT, 1)
k_all(const float* __restrict__ x, const float* __restrict__ wp,
      float* __restrict__ out) {
    const int tid = threadIdx.x;
    const int b0  = blockIdx.x * BPB;
    const int nb  = min(BPB, BB - b0);
    const int nchunk = nb * SS * 2;

    __shared__ float s_feat[BPB][SS][5];  // features 10..13 (+pad; 5 coprime 32 banks)
    __shared__ float s_y[BPB][4];

    // ---- phase 1: front-batch ALL chunk loads into registers ----
    float4 ch[ITERS];
#pragma unroll
    for (int k = 0; k < ITERS; k++) {
        int i = tid + k * NT;
        if (i < nchunk) {
            int rg   = i >> 1;            // row index within block (0..nb*300-1)
            int half = i & 1;             // 0: f8..f11, 1: f12..f15
            int bl = rg / SS, r = rg - bl * SS;
            const float* base = x + (size_t)(b0 + bl) * (TT * FF) + r * FF;
            ch[k] = *reinterpret_cast<const float4*>(base + 8 + half * 4);
        }
    }

    // ---- phase 2: y_j once per (b,j), overlapped with in-flight loads ----
    if (tid < nb * 4) {
        int bl = tid >> 2;
        int j  = (tid & 3) + 1;
        const float* xl = x + (size_t)(b0 + bl) * (TT * FF) + (size_t)(TT - 1) * FF;
        float w = *wp;
        float d = xl[0];
        for (int k = 1; k < j; k++) d = __fadd_rn(d, xl[k]);  // sequential prefix sum
        float den = __fadd_rn(w, __fmul_rn(xl[4 + j], 25.0f));
        float td  = __fdiv_rn(__fmul_rn(d, 150.0f), den);
        s_y[bl][j - 1] = __fmul_rn(td, 10.0f);
    }

    // ---- phase 3: drain registers into smem (2 useful floats per chunk) ----
#pragma unroll
    for (int k = 0; k < ITERS; k++) {
        int i = tid + k * NT;
        if (i < nchunk) {
            int rg   = i >> 1;
            int half = i & 1;
            int bl = rg / SS, r = rg - bl * SS;
            if (half == 0) {
                s_feat[bl][r][0] = ch[k].z;   // f10
                s_feat[bl][r][1] = ch[k].w;   // f11
            } else {
                s_feat[bl][r][2] = ch[k].x;   // f12
                s_feat[bl][r][3] = ch[k].y;   // f13
            }
        }
    }
    __syncthreads();

    // ---- gather into registers; mask ORed over this block's b's ----
    const int  s    = tid;            // one step per thread; NT >= SS covers all
    const bool owns = (s < SS);

    float4   vals[BPB];
    unsigned msk = 0u;

    if (owns) {
        float sf = (float)s;
#pragma unroll
        for (int bl = 0; bl < BPB; bl++) {
            if (bl >= nb) break;
            int r0 = min(max((int)__fsub_rn(sf, s_y[bl][0]), 0), SS - 1);
            int r1 = min(max((int)__fsub_rn(sf, s_y[bl][1]), 0), SS - 1);
            int r2 = min(max((int)__fsub_rn(sf, s_y[bl][2]), 0), SS - 1);
            int r3 = min(max((int)__fsub_rn(sf, s_y[bl][3]), 0), SS - 1);
            float4 o;
            o.x = s_feat[bl][r0][0];
            o.y = s_feat[bl][r1][1];
            o.z = s_feat[bl][r2][2];
            o.w = s_feat[bl][r3][3];
            vals[bl] = o;
            msk |= (o.x != 0.0f ? 1u : 0u) | (o.y != 0.0f ? 2u : 0u) |
                   (o.z != 0.0f ? 4u : 0u) | (o.w != 0.0f ? 8u : 0u);
        }
        if (msk) atomicOr(&g_state.mask[s].v, msk);   // own 128B line per step
    }

    // ---- grid barrier (147 arrivals, all blocks co-resident at occ 1) ----
    __threadfence();
    __syncthreads();
    if (tid == 0) {
        atomicAdd(&g_state.arrive, 1u);
        volatile unsigned* av = &g_state.arrive;
        while (*av < (unsigned)GRID) { __nanosleep(32); }
        __threadfence();
    }
    __syncthreads();

    // ---- emit from registers (stores coalesced in s) ----
    if (owns) {
        unsigned mm = __ldcg(&g_state.mask[s].v);
        int sel = mm ? (__ffs(mm) - 1) : -1;
#pragma unroll
        for (int bl = 0; bl < BPB; bl++) {
            if (bl >= nb) break;
            float4 o = vals[bl];
            float r = 0.0f;
            r = (sel == 0) ? o.x : r;
            r = (sel == 1) ? o.y : r;
            r = (sel == 2) ? o.z : r;
            r = (sel == 3) ? o.w : r;
            out[(size_t)(b0 + bl) * SS + s] = r;
        }
    }
}

extern "C" void kernel_launch(void* const* d_in, const int* in_sizes, int n_in,
                              void* d_out, int out_size) {
    // metadata order: vi(0), delta_y(1), v_previous(2), x_input(3), w(4)
    const float* x = (const float*)d_in[3];
    const float* w = (const float*)d_in[4];
    float* out = (float*)d_out;

    void* statep = nullptr;
    cudaGetSymbolAddress(&statep, g_state);
    cudaMemsetAsync(statep, 0, sizeof(SyncState));   // graph memset node

    k_all<<<GRID, NT>>>(x, w, out);
}